// round 13
// baseline (speedup 1.0000x reference)
#include <cuda_runtime.h>
#include <cuda_bf16.h>

#define VOCAB    128000
#define HISTLEN  2048
#define TOPK     15
#define NBLK     125           // 125 blocks * 256 thr * 4 elem == 128000 exactly
#define NTHR     256
#define NWARP    (NTHR / 32)   // 8
#define NEG_KEY  0ull

// -------- device scratch (allocations forbidden; ALL self-cleaning) --------
// Invariant at every launch entry: g_bitmap==0, g_cnt*==0, g_amax==0.
// Static zero-init establishes it; every call restores it before exit.
__device__ unsigned           g_bitmap[VOCAB / 32];
__device__ unsigned long long g_btop[NBLK * TOPK];
__device__ float              g_lmax, g_pivot, g_S;
__device__ unsigned long long g_amax;
__device__ unsigned           g_cnt1, g_cnt2, g_cnt3;
__device__ volatile unsigned  g_gen1, g_gen2;      // monotonic generations

// monotone map float -> unsigned (total order; NaN above +inf) + inverse
__device__ __forceinline__ unsigned ordered(float f) {
    unsigned u = __float_as_uint(f);
    return u ^ ((u & 0x80000000u) ? 0xFFFFFFFFu : 0x80000000u);
}
__device__ __forceinline__ float unordered(unsigned x) {
    unsigned u = (x & 0x80000000u) ? (x ^ 0x80000000u) : (x ^ 0xFFFFFFFFu);
    return __uint_as_float(u);
}
__device__ __forceinline__ unsigned long long make_key(float v, int i) {
    return ((unsigned long long)ordered(v) << 32)
         | (unsigned long long)(0xFFFFFFFFu - (unsigned)i);
}
__device__ __forceinline__ unsigned long long warp_max(unsigned long long k) {
    #pragma unroll
    for (int off = 16; off; off >>= 1) {
        unsigned long long o = __shfl_xor_sync(0xffffffffu, k, off);
        if (o > k) k = o;
    }
    return k;
}

// extract current max of shared slice [lo,hi) (warp-collective), pop it
__device__ __forceinline__ unsigned long long
slice_extract(volatile unsigned long long* arr, int lo, int hi, int lane) {
    unsigned long long lm = NEG_KEY; int lp = lo;
    for (int j = lo + lane; j < hi; j += 32) {
        unsigned long long x = arr[j];
        if (x > lm) { lm = x; lp = j; }
    }
    unsigned long long m = warp_max(lm);
    if (lm == m && lm != NEG_KEY) arr[lp] = NEG_KEY;   // unique keys: one owner
    __syncwarp();
    return m;
}

__global__ void __launch_bounds__(NTHR, 1)
k_fused(const float* __restrict__ logits, const int* __restrict__ y,
        const float* __restrict__ noise, float* __restrict__ out, int out_size) {
    __shared__ unsigned long long sall[NBLK * TOPK];   // 15000 B (merge block)
    __shared__ unsigned long long swtop[NWARP * TOPK]; // 960 B
    __shared__ unsigned long long red[NWARP];
    __shared__ int s_flag;

    const int tid = threadIdx.x, lane = tid & 31, w = tid >> 5;
    const int gtid = blockIdx.x * NTHR + tid;
    const int base = gtid * 4;

    // ---- early vector loads (independent of bitmap) — hide DRAM latency ----
    float4 raw = *(const float4*)(logits + base);
    float4 nz  = *(const float4*)(noise  + base);

    // ---- phase 0: membership scatter + y copy (first 2048 global threads) --
    if (gtid < HISTLEN) {
        int p = y[gtid];
        if (out_size >= HISTLEN + 2) out[1 + gtid] = (float)p;  // exact < 2^24
        p = min(max(p, 0), VOCAB - 1);                // clamp: OOB impossible
        atomicOr(&g_bitmap[p >> 5], 1u << (p & 31));
    }

    // ---- grid barrier 1 ----------------------------------------------------
    __syncthreads();
    if (tid == 0) {
        __threadfence();
        unsigned gen = g_gen1;
        if (atomicAdd(&g_cnt1, 1u) == NBLK - 1) {
            g_cnt1 = 0u; __threadfence(); g_gen1 = gen + 1u;
        } else {
            while (g_gen1 == gen) __nanosleep(32);
        }
    }
    __syncthreads();

    // ---- phase 1: penalty (regs) + exact per-block top-15 -------------------
    // _rn ops are bit-identical to the f32 reference; value depends only on the
    // ORIGINAL logit so duplicate history tokens are harmless.
    {
        unsigned bw = g_bitmap[base >> 5];            // first touch post-barrier
        unsigned sh = (unsigned)(base & 31);
        if ((bw >> (sh + 0)) & 1u) raw.x = (raw.x < 0.f) ? __fmul_rn(raw.x, 1.35f) : __fdiv_rn(raw.x, 1.35f);
        if ((bw >> (sh + 1)) & 1u) raw.y = (raw.y < 0.f) ? __fmul_rn(raw.y, 1.35f) : __fdiv_rn(raw.y, 1.35f);
        if ((bw >> (sh + 2)) & 1u) raw.z = (raw.z < 0.f) ? __fmul_rn(raw.z, 1.35f) : __fdiv_rn(raw.z, 1.35f);
        if ((bw >> (sh + 3)) & 1u) raw.w = (raw.w < 0.f) ? __fmul_rn(raw.w, 1.35f) : __fdiv_rn(raw.w, 1.35f);
    }
    {
        unsigned long long k0 = make_key(raw.x, base + 0);
        unsigned long long k1 = make_key(raw.y, base + 1);
        unsigned long long k2 = make_key(raw.z, base + 2);
        unsigned long long k3 = make_key(raw.w, base + 3);
        #pragma unroll
        for (int k = 0; k < TOPK; k++) {              // warp top-15 of 128 keys
            unsigned long long lm = k0;
            if (k1 > lm) lm = k1;
            if (k2 > lm) lm = k2;
            if (k3 > lm) lm = k3;
            unsigned long long m = warp_max(lm);
            if (lane == 0) swtop[w * TOPK + k] = m;
            if (k0 == m) k0 = NEG_KEY;                // unique: exactly one pops
            else if (k1 == m) k1 = NEG_KEY;
            else if (k2 == m) k2 = NEG_KEY;
            else if (k3 == m) k3 = NEG_KEY;
        }
        __syncthreads();
        if (w == 0) {                                 // 120 -> block top-15
            for (int k = 0; k < TOPK; k++) {
                unsigned long long m = slice_extract(swtop, 0, NWARP * TOPK, lane);
                if (lane == 0) g_btop[blockIdx.x * TOPK + k] = m;
            }
        }
        __syncthreads();
    }

    // ---- grid barrier 2 with FOLDED MERGE (last arriver merges, releases) ---
    if (tid == 0) {
        __threadfence();                              // publish g_btop stores
        unsigned gen = g_gen2;
        s_flag = (atomicAdd(&g_cnt2, 1u) == NBLK - 1);
        if (!s_flag) { while (g_gen2 == gen) __nanosleep(32); }
    }
    __syncthreads();
    if (s_flag) {                                     // merging block
        __threadfence();                              // acquire all g_btop
        for (int j = tid; j < NBLK * TOPK; j += NTHR) sall[j] = g_btop[j];
        __syncthreads();
        {   // level 1: 8 warps, top-15 of ~235-key slices
            int lo = w * 235, hi = min(lo + 235, NBLK * TOPK);
            for (int k = 0; k < TOPK; k++) {
                unsigned long long m = slice_extract(sall, lo, hi, lane);
                if (lane == 0) swtop[w * TOPK + k] = m;
            }
        }
        __syncthreads();
        if (w == 0) {                                 // level 2: 120 -> 15
            float top[TOPK];
            for (int k = 0; k < TOPK; k++) {
                unsigned long long m = slice_extract(swtop, 0, NWARP * TOPK, lane);
                top[k] = unordered((unsigned)(m >> 32));
            }
            if (lane == 0) {
                float lmax = top[0];
                float S = 0.0f;                       // kept set IS these 15
                for (int k = 0; k < TOPK; k++) S += expf(top[k] - lmax);
                g_lmax = lmax; g_pivot = top[TOPK - 1]; g_S = S;
            }
        }
        __syncthreads();
        if (tid == 0) {                               // release spinners
            g_cnt2 = 0u; __threadfence(); g_gen2 = g_gen2 + 1u;
        }
    }
    __syncthreads();
    __threadfence();                                  // order pivot loads below

    // ---- phase 2: argmax(probs/noise) from REGISTERS ------------------------
    // kept: (exp(l-lmax)/S)/noise ; masked: 0/noise (exact +-0 / NaN like ref).
    // +-0 unify to ONE key (first-index ties, IEEE +0==-0 under jnp.argmax);
    // NaN keys order above everything (NaN propagation).
    const float piv = g_pivot, lmax = g_lmax, S = g_S;
    auto key_of = [&](float lv, float nv, int i) -> unsigned long long {
        float v = (lv >= piv) ? __fdiv_rn(__fdiv_rn(expf(lv - lmax), S), nv)
                              : __fdiv_rn(0.0f, nv);
        unsigned ov = (v == 0.0f) ? 0x80000000u : ordered(v);
        return ((unsigned long long)ov << 32)
             | (unsigned long long)(0xFFFFFFFFu - (unsigned)i);
    };
    unsigned long long b = key_of(raw.x, nz.x, base + 0);
    { unsigned long long t = key_of(raw.y, nz.y, base + 1); if (t > b) b = t; }
    { unsigned long long t = key_of(raw.z, nz.z, base + 2); if (t > b) b = t; }
    { unsigned long long t = key_of(raw.w, nz.w, base + 3); if (t > b) b = t; }
    b = warp_max(b);
    if (lane == 0) red[w] = b;
    // self-clean own bitmap words (only this block ever reads them)
    if ((tid & 7) == 0) g_bitmap[base >> 5] = 0u;
    __syncthreads();
    if (w == 0) {
        unsigned long long m = (lane < NWARP) ? red[lane] : NEG_KEY;
        m = warp_max(m);
        if (lane == 0) atomicMax(&g_amax, m);
    }
    __syncthreads();

    // ---- exit counter: last block writes the sample (no spin) ---------------
    if (tid == 0) {
        __threadfence();
        if (atomicAdd(&g_cnt3, 1u) == NBLK - 1) {
            g_cnt3 = 0u;                              // self-clean
            unsigned long long m = atomicAdd(&g_amax, 0ull);  // coherent read
            g_amax = 0ull;                            // self-clean
            float fidx = (float)(int)(0xFFFFFFFFu - (unsigned)(m & 0xFFFFFFFFull));
            out[0] = fidx;                                    // samples
            if (out_size >= HISTLEN + 2) out[1 + HISTLEN] = fidx;  // y_new tail
            for (int j = HISTLEN + 2; j < out_size; j++) out[j] = fidx;
        }
    }
}

extern "C" void kernel_launch(void* const* d_in, const int* in_sizes, int n_in,
                              void* d_out, int out_size) {
    // y = the size-2048 tensor; among the remaining two (metadata order),
    // logits precedes noise (validated rounds 9-12).
    int iy = 1;
    for (int i = 0; i < n_in; i++) if (in_sizes[i] == HISTLEN) { iy = i; break; }
    int fl[2]; int nf = 0;
    for (int i = 0; i < n_in && nf < 2; i++) if (i != iy) fl[nf++] = i;

    const float* logits = (const float*)d_in[fl[0]];
    const float* noise  = (const float*)d_in[fl[1]];
    const int*   y      = (const int*)d_in[iy];

    k_fused<<<NBLK, NTHR>>>(logits, y, noise, (float*)d_out, out_size);
}